// round 9
// baseline (speedup 1.0000x reference)
#include <cuda_runtime.h>

// Lookahead depthwise conv (scatter form, dynamic-balanced tiling):
//   out[t,b,f] = sum_{k=0..20} x[t+k,b,f] * w[f,k],  x[t+k>=S] = 0
// x: (2048, 32, 1024) fp32, w: (1024, 21) fp32, out same shape as x.
//
// 1024 independent blocks (128 lane-chunks x 8 t-segments of 256), one tile
// per block. 1.73 waves at 4 blocks/SM -> hardware work-steal balances the
// per-SM load to ~4%. Interior segments (s<7) use unconditional loads
// (provably in-bounds) so ptxas can cluster them; only s=7 pays the guard.

#define S_LEN   2048
#define NBATCH  32
#define NFEAT   1024
#define TAPS    21
#define BF      (NBATCH * NFEAT)      /* 32768 floats per t-slice */
#define PAIRS   (BF / 2)              /* 16384 f32x2 lanes per slice */
#define SPLIT   8
#define TSEG    (S_LEN / SPLIT)       /* 256 outputs per segment */
#define PIPE    7                     /* prefetch depth; divides 21 */
#define TPB     128
#define CHUNKS  (PAIRS / TPB)         /* 128 lane-chunks */
#define NTILES  (CHUNKS * SPLIT)      /* 1024 = grid size */
#define NMAIN   12                    /* full 21-step chunks after warmup */
#define NTAIL   3                     /* 21 + 12*21 + 3 = 276 = TSEG + 20 */

typedef unsigned long long u64;

__device__ __forceinline__ u64 ffma2(u64 a, u64 b, u64 c) {
    u64 d;
    asm("fma.rn.f32x2 %0, %1, %2, %3;" : "=l"(d) : "l"(a), "l"(b), "l"(c));
    return d;
}
__device__ __forceinline__ u64 fmul2(u64 a, u64 b) {
    u64 d;
    asm("mul.rn.f32x2 %0, %1, %2;" : "=l"(d) : "l"(a), "l"(b));
    return d;
}
__device__ __forceinline__ u64 pack2(float lo, float hi) {
    u64 d;
    asm("mov.b64 %0, {%1, %2};" : "=l"(d) : "f"(lo), "f"(hi));
    return d;
}
// Default-cached 64-bit load: halo slices are re-read by the neighboring
// segment's block, so keep them L2-evictable-normal.
__device__ __forceinline__ u64 ldg64(const float* p) {
    u64 v;
    asm("ld.global.b64 %0, [%1];" : "=l"(v) : "l"(p));
    return v;
}
// Streaming store: out is written once, never re-read.
__device__ __forceinline__ void stcs64(float* p, u64 v) {
    asm("st.global.cs.b64 [%0], %1;" :: "l"(p), "l"(v) : "memory");
}

// One scatter step. Rn/Qn fold to literals after unrolling (21 % 7 == 0).
// k=20 tap completes the oldest output (optionally stored); k=19..1
// accumulate; k=0 re-initializes the freed slot via MUL.
#define STEP(Rn, DO_STORE, DO_LOAD)                                          \
  do {                                                                       \
    const int R_ = (Rn) % TAPS;                                              \
    const int Q_ = (Rn) % PIPE;                                              \
    u64 xv_ = pipe[Q_];                                                      \
    if (DO_LOAD) {                                                           \
      u64 nv_;                                                               \
      if (GUARD) {                                                           \
        nv_ = 0ull;                                                          \
        if (live > 0) nv_ = ldg64(ldp);                                      \
        --live;                                                              \
      } else {                                                               \
        nv_ = ldg64(ldp);                                                    \
      }                                                                      \
      ldp += BF;                                                             \
      pipe[Q_] = nv_;                                                        \
    }                                                                        \
    const int DONE_ = (R_ + 1) % TAPS;                                       \
    acc[DONE_] = ffma2(xv_, wk[TAPS - 1], acc[DONE_]);                       \
    if (DO_STORE) {                                                          \
      stcs64(stp, acc[DONE_]);                                               \
      stp += BF;                                                             \
    }                                                                        \
    _Pragma("unroll")                                                        \
    for (int k_ = 1; k_ < TAPS; ++k_)                                        \
      acc[(R_ - k_ + 2 * TAPS) % TAPS] =                                     \
          ffma2(xv_, wk[k_], acc[(R_ - k_ + 2 * TAPS) % TAPS]);              \
    acc[R_] = fmul2(xv_, wk[0]);                                             \
  } while (0)

template <bool GUARD>
__device__ __forceinline__ void run_segment(const float* __restrict__ xin,
                                            float* __restrict__ stp,
                                            const u64* __restrict__ wk,
                                            int live)
{
    // Preload pipe with x[t0 .. t0+6] (max t0+6 = 1798 < 2048, always valid).
    u64 pipe[PIPE];
#pragma unroll
    for (int i = 0; i < PIPE; ++i)
        pipe[i] = ldg64(xin + i * BF);

    u64 acc[TAPS];
#pragma unroll
    for (int j = 0; j < TAPS; ++j) acc[j] = 0ull;

    const float* ldp = xin + PIPE * BF;

    // Warmup: n = 0..20; only n==20 stores (completes out[t0]).
#pragma unroll
    for (int n = 0; n < TAPS; ++n)
        STEP(n, n == TAPS - 1, true);

    // Main: 12 x 21 steps (n = 21..272); all store, all load.
    // Interior: max load t = t0 + 272 + 7 <= 1536+279 = 1815 < 2048.
    for (int c = 0; c < NMAIN; ++c) {
#pragma unroll
        for (int r = 0; r < TAPS; ++r)
            STEP(r, true, true);
    }

    // Tail: n = 273..275 (R=0,1,2; Q aligned since 273 % 7 == 0). No loads.
#pragma unroll
    for (int r = 0; r < NTAIL; ++r)
        STEP(r, true, false);
}

__global__ void __launch_bounds__(TPB, 4)
lookahead_kernel(const float* __restrict__ x,
                 const float* __restrict__ w,
                 float* __restrict__ out)
{
    const unsigned c = blockIdx.x & (CHUNKS - 1);   // lane-chunk
    const unsigned s = blockIdx.x >> 7;             // t-segment (CHUNKS=128)
    const unsigned p = c * TPB + threadIdx.x;       // pair id
    const unsigned base = 2u * p;                   // float offset in slice
    const unsigned f0 = base & (NFEAT - 1);

    // Per-thread packed weights: wk[k] = (w[f0][k], w[f0+1][k])
    u64 wk[TAPS];
#pragma unroll
    for (int k = 0; k < TAPS; ++k)
        wk[k] = pack2(w[f0 * TAPS + k], w[(f0 + 1) * TAPS + k]);

    const unsigned t0 = s * TSEG;
    const float* xin = x + (size_t)t0 * BF + base;
    float* stp = out + (size_t)t0 * BF + base;

    if (s < SPLIT - 1) {
        run_segment<false>(xin, stp, wk, 0);
    } else {
        // Loads valid while step n satisfies t0 + n + PIPE < S_LEN.
        run_segment<true>(xin, stp, wk, (int)(S_LEN - t0) - PIPE);
    }
}

extern "C" void kernel_launch(void* const* d_in, const int* in_sizes, int n_in,
                              void* d_out, int out_size)
{
    const float* x = (const float*)d_in[0];   // (2048, 32, 1024) fp32
    const float* w = (const float*)d_in[1];   // (1024, 21) fp32
    float* out = (float*)d_out;               // (2048, 32, 1024) fp32

    lookahead_kernel<<<NTILES, TPB>>>(x, w, out);
}

// round 11
// speedup vs baseline: 1.0907x; 1.0907x over previous
#include <cuda_runtime.h>

// Lookahead depthwise conv, scatter form + cp.async smem-staged input stream:
//   out[t,b,f] = sum_{k=0..20} x[t+k,b,f] * w[f,k],  x[t+k>=S] = 0
// x: (2048, 32, 1024) fp32, w: (1024, 21) fp32, out same shape as x.
//
// Diagnosis R3..R7: DRAM stuck at ~57-64% with occ 21% / issue 23% =>
// latency-bound; register pipe caps in-flight loads at ~6/warp (25 KB/SM).
// Fix: 15 outstanding cp.async (LDGSTS) per thread into a 16-stage smem
// ring (16 KB/CTA) -> ~61 KB/SM in flight, registers unchanged.
// R10 bug: ring LDS was non-volatile asm -> compiler hoisted it above
// cp.async.wait_group (read-before-write). Now volatile + memory clobber.

#define S_LEN   2048
#define NBATCH  32
#define NFEAT   1024
#define TAPS    21
#define BF      (NBATCH * NFEAT)      /* 32768 floats per t-slice */
#define PAIRS   (BF / 2)              /* 16384 f32x2 lanes per slice */
#define SPLIT   8
#define TSEG    (S_LEN / SPLIT)       /* 256 outputs per segment */
#define TPB     128
#define CHUNKS  (PAIRS / TPB)         /* 128 lane-chunks */
#define NTILES  (CHUNKS * SPLIT)      /* 1024 = grid size */
#define NSTEPS  (TSEG + TAPS - 1)     /* 276 consumed slices per tile */
#define D0      15                    /* cp.async prefetch distance */
#define DSTAGE  16                    /* smem ring stages (power of 2) */
#define RINGB   (DSTAGE * TPB * 8)    /* 16384 bytes per CTA */
#define RMASK   (RINGB - 1)
#define NMAIN   12                    /* 21 warmup + 12*21 + 3 = 276 */
#define NTAIL   3

typedef unsigned long long u64;

__device__ __forceinline__ u64 ffma2(u64 a, u64 b, u64 c) {
    u64 d;
    asm("fma.rn.f32x2 %0, %1, %2, %3;" : "=l"(d) : "l"(a), "l"(b), "l"(c));
    return d;
}
__device__ __forceinline__ u64 fmul2(u64 a, u64 b) {
    u64 d;
    asm("mul.rn.f32x2 %0, %1, %2;" : "=l"(d) : "l"(a), "l"(b));
    return d;
}
__device__ __forceinline__ u64 pack2(float lo, float hi) {
    u64 d;
    asm("mov.b64 %0, {%1, %2};" : "=l"(d) : "f"(lo), "f"(hi));
    return d;
}
// VOLATILE smem ring load: must not be hoisted above cp.async.wait_group
// (the ring is written asynchronously by LDGSTS).
__device__ __forceinline__ u64 lds64(unsigned a) {
    u64 v;
    asm volatile("ld.shared.b64 %0, [%1];" : "=l"(v) : "r"(a) : "memory");
    return v;
}
// cp.async, 8 bytes, unconditional.
#define CP8(dst, src)                                                        \
    asm volatile("cp.async.ca.shared.global [%0], [%1], 8;"                  \
                 :: "r"(dst), "l"(src) : "memory")
// cp.async with runtime src-size (0 => zero-fill, no global read).
#define CP8Z(dst, src, sz)                                                   \
    asm volatile("cp.async.ca.shared.global [%0], [%1], 8, %2;"              \
                 :: "r"(dst), "l"(src), "r"(sz) : "memory")
#define CPCOMMIT() asm volatile("cp.async.commit_group;" ::: "memory")
#define CPWAIT(n)  asm volatile("cp.async.wait_group %0;" :: "n"(n) : "memory")

// One scatter step. Rn folds to a literal after unrolling.
// LMODE: 0 = no load, 1 = unconditional load, 2 = size-guarded load.
// Every step commits a group (empty ones keep wait_group counting aligned)
// and prefetches xv for the NEXT step from the smem ring.
#define STEP(Rn, DO_STORE, LMODE)                                            \
  do {                                                                       \
    const int R_ = (Rn) % TAPS;                                              \
    u64 xv_ = xv_next;                                                       \
    if ((LMODE) == 1) {                                                      \
      CP8(sbase + woff, ldp);                                                \
      ldp += BF;                                                             \
      woff = (woff + TPB * 8) & RMASK;                                       \
    } else if ((LMODE) == 2) {                                               \
      unsigned sz_ = (live > 0) ? 8u : 0u;                                   \
      --live;                                                                \
      CP8Z(sbase + woff, ldp, sz_);                                          \
      ldp += BF;                                                             \
      woff = (woff + TPB * 8) & RMASK;                                       \
    }                                                                        \
    CPCOMMIT();                                                              \
    const int DONE_ = (R_ + 1) % TAPS;                                       \
    acc[DONE_] = ffma2(xv_, wk[TAPS - 1], acc[DONE_]);                       \
    if (DO_STORE) {                                                          \
      *reinterpret_cast<u64*>(stp) = acc[DONE_];                             \
      stp += BF;                                                             \
    }                                                                        \
    _Pragma("unroll")                                                        \
    for (int k_ = 1; k_ < TAPS; ++k_)                                        \
      acc[(R_ - k_ + 2 * TAPS) % TAPS] =                                     \
          ffma2(xv_, wk[k_], acc[(R_ - k_ + 2 * TAPS) % TAPS]);              \
    acc[R_] = fmul2(xv_, wk[0]);                                             \
    CPWAIT(D0 - 1);                                                          \
    xv_next = lds64(sbase + roff);                                           \
    roff = (roff + TPB * 8) & RMASK;                                         \
  } while (0)

template <bool GUARD>
__device__ __forceinline__ void run_segment(const float* __restrict__ xin,
                                            float* __restrict__ stp,
                                            const u64* __restrict__ wk,
                                            int live, unsigned sbase)
{
    const float* ldp = xin;       // next slice to prefetch
    unsigned woff = 0, roff = 0;

    // Prologue: issue D0=15 slices (t0..t0+14; max t0+14 = 1806 < 2048,
    // always in-bounds), one commit group each.
#pragma unroll
    for (int i = 0; i < D0; ++i) {
        CP8(sbase + woff, ldp);
        CPCOMMIT();
        ldp += BF;
        woff = (woff + TPB * 8) & RMASK;
    }
    CPWAIT(D0 - 1);                       // group 0 complete
    u64 xv_next = lds64(sbase + roff);    // slice 0
    roff = (roff + TPB * 8) & RMASK;

    u64 acc[TAPS];
#pragma unroll
    for (int j = 0; j < TAPS; ++j) acc[j] = 0ull;

    if (GUARD) {
        // s=7: every load size-guarded by the t<2048 countdown.
#pragma unroll
        for (int n = 0; n < TAPS; ++n)
            STEP(n, n == TAPS - 1, 2);
        for (int c = 0; c < NMAIN; ++c) {
#pragma unroll
            for (int r = 0; r < TAPS; ++r)
                STEP(r, true, 2);
        }
    } else {
        // Interior: slices t0+15..t0+266 provably < 2048 -> unconditional.
#pragma unroll
        for (int n = 0; n < TAPS; ++n)
            STEP(n, n == TAPS - 1, 1);
        for (int c = 0; c < NMAIN - 1; ++c) {
#pragma unroll
            for (int r = 0; r < TAPS; ++r)
                STEP(r, true, 1);
        }
        // Last main chunk (n = 252..272): only 9 real slices remain
        // (267..275); size-guard the rest so reads stop at NSTEPS.
        live = NSTEPS - D0 - (TAPS + (NMAIN - 1) * TAPS);  // = 9
#pragma unroll
        for (int r = 0; r < TAPS; ++r)
            STEP(r, true, 2);
    }

    // Tail: n = 273..275; no loads (empty commit groups keep counts aligned).
#pragma unroll
    for (int r = 0; r < NTAIL; ++r)
        STEP(r, true, 0);
}

__global__ void __launch_bounds__(TPB, 4)
lookahead_kernel(const float* __restrict__ x,
                 const float* __restrict__ w,
                 float* __restrict__ out)
{
    __shared__ __align__(16) char ring[RINGB];

    const unsigned c = blockIdx.x & (CHUNKS - 1);   // lane-chunk
    const unsigned s = blockIdx.x >> 7;             // t-segment (CHUNKS=128)
    const unsigned p = c * TPB + threadIdx.x;       // pair id
    const unsigned base = 2u * p;                   // float offset in slice
    const unsigned f0 = base & (NFEAT - 1);

    // Per-thread smem column base (each thread streams its own 8B column).
    const unsigned sbase =
        (unsigned)__cvta_generic_to_shared(ring) + threadIdx.x * 8u;

    // Per-thread packed weights: wk[k] = (w[f0][k], w[f0+1][k])
    u64 wk[TAPS];
#pragma unroll
    for (int k = 0; k < TAPS; ++k)
        wk[k] = pack2(w[f0 * TAPS + k], w[(f0 + 1) * TAPS + k]);

    const unsigned t0 = s * TSEG;
    const float* xin = x + (size_t)t0 * BF + base;
    float* stp = out + (size_t)t0 * BF + base;

    if (s < SPLIT - 1) {
        run_segment<false>(xin, stp, wk, 0, sbase);
    } else {
        // Real loads while slice index i = n + D0 satisfies t0 + i < S_LEN.
        run_segment<true>(xin, stp, wk, (int)(S_LEN - t0) - D0, sbase);
    }
}

extern "C" void kernel_launch(void* const* d_in, const int* in_sizes, int n_in,
                              void* d_out, int out_size)
{
    const float* x = (const float*)d_in[0];   // (2048, 32, 1024) fp32
    const float* w = (const float*)d_in[1];   // (1024, 21) fp32
    float* out = (float*)d_out;               // (2048, 32, 1024) fp32

    lookahead_kernel<<<NTILES, TPB>>>(x, w, out);
}